// round 1
// baseline (speedup 1.0000x reference)
#include <cuda_runtime.h>

#define IN_C   64
#define OUT_C  128
#define HWID   48
#define IMG    2304        // 48*48
#define IN_DIM 576
#define NROWS  36864       // 16 * 2304
#define NF     9           // silu + 8 spline bases per d
#define TM     64          // rows per CTA
#define DCH    16          // d-values per chunk
#define NCHUNK (IN_DIM / DCH)

// Packed weight tensor: W[d][j][o], j=0 -> base weight, j=1..8 -> spline_weight*scaler
__device__ __align__(16) float g_Wall[IN_DIM * NF * OUT_C];

__global__ void prep_weights_kernel(const float* __restrict__ Wb,
                                    const float* __restrict__ Ws,
                                    const float* __restrict__ Sc) {
    int idx = blockIdx.x * blockDim.x + threadIdx.x;
    if (idx >= IN_DIM * NF * OUT_C) return;
    int o = idx & (OUT_C - 1);
    int j = (idx >> 7) % NF;
    int d = idx / (NF * OUT_C);
    float v;
    if (j == 0) v = Wb[o * IN_DIM + d];
    else        v = Ws[(o * IN_DIM + d) * 8 + (j - 1)] * Sc[o * IN_DIM + d];
    g_Wall[idx] = v;
}

__device__ __forceinline__ unsigned long long pack2(float a, float b) {
    unsigned long long r;
    asm("mov.b64 %0, {%1, %2};" : "=l"(r) : "f"(a), "f"(b));
    return r;
}
__device__ __forceinline__ unsigned long long ffma2(unsigned long long a,
                                                    unsigned long long b,
                                                    unsigned long long c) {
    unsigned long long d;
    asm("fma.rn.f32x2 %0, %1, %2, %3;" : "=l"(d) : "l"(a), "l"(b), "l"(c));
    return d;
}
__device__ __forceinline__ float2 unpack2(unsigned long long a) {
    float x, y;
    asm("mov.b64 {%0, %1}, %2;" : "=f"(x), "=f"(y) : "l"(a));
    return make_float2(x, y);
}

__global__ __launch_bounds__(256, 2)
void convkan_fused_kernel(const float* __restrict__ x, float* __restrict__ out) {
    // feat[(dl*NF + j)*TM + r]
    __shared__ __align__(16) float feat[DCH * NF * TM];

    const int tid  = threadIdx.x;
    const int lane = tid & 31;
    const int warp = tid >> 5;
    const int row_base = blockIdx.x * TM;

    // ---- per-thread phase-A element constants (4 elements/thread, constant across chunks) ----
    int ra[4], dla[4], cbase[4], kha[4], kwa[4], lba[4];
    #pragma unroll
    for (int i = 0; i < 4; i++) {
        int e  = tid + 256 * i;
        int r  = e & (TM - 1);
        int dl = e >> 6;
        int n  = row_base + r;
        int b  = n / IMG;
        int nl = n - b * IMG;
        int i0 = nl >> 2;           // fixed feature channel (c, kh, kw) for this row
        int c  = i0 / 9;
        int t9 = i0 - c * 9;
        int kh = t9 / 3;
        ra[i]    = r;
        dla[i]   = dl;
        cbase[i] = (b * IN_C + c) * IMG;
        kha[i]   = kh;
        kwa[i]   = t9 - kh * 3;
        lba[i]   = (nl & 3) * IN_DIM + dl;   // spatial index base within 48x48 image
    }

    unsigned long long acc[4][4];
    #pragma unroll
    for (int oi = 0; oi < 4; oi++)
        #pragma unroll
        for (int p = 0; p < 4; p++) acc[oi][p] = 0ull;

    const int o4 = lane * 4;     // 4 consecutive output channels per thread
    const int rb = warp * 8;     // 8 rows per warp-group

    for (int ch = 0; ch < NCHUNK; ch++) {
        __syncthreads();   // previous phase-B consumers done before overwrite
        // ================= phase A: build activated features into SMEM =================
        #pragma unroll
        for (int i = 0; i < 4; i++) {
            int l  = lba[i] + ch * DCH;
            int h  = l / HWID;
            int w  = l - h * HWID;
            int hh = h + kha[i] - 1;
            int ww = w + kwa[i] - 1;
            float v = 0.f;
            if ((unsigned)hh < (unsigned)HWID && (unsigned)ww < (unsigned)HWID)
                v = __ldg(x + cbase[i] + hh * HWID + ww);

            float* fp = feat + dla[i] * (NF * TM) + ra[i];
            // silu(v) = v * sigmoid(v)
            float e  = __expf(-v);
            fp[0] = __fdividef(v, 1.f + e);
            // dense 8-wide cubic B-spline basis (uniform extended grid, h=0.4, lo=-1)
            #pragma unroll
            for (int t = 1; t <= 8; t++) fp[t * TM] = 0.f;
            float s  = fmaf(v, 2.5f, 5.5f);          // (v - lo)/h + 3
            float fm = floorf(s);
            int   m  = (int)fm;
            if ((unsigned)m <= 10u) {                // inside extended knot span
                float f   = s - fm;
                float f2  = f * f, f3 = f2 * f;
                float omf = 1.f - f;
                float q0 = omf * omf * omf * (1.f / 6.f);        // basis m-3
                float q1 = (2.f / 3.f) - f2 + 0.5f * f3;          // basis m-2
                float q2 = (1.f / 6.f) + 0.5f * (f + f2 - f3);    // basis m-1
                float q3 = f3 * (1.f / 6.f);                      // basis m
                int t0 = m - 3;
                if ((unsigned)(t0    ) < 8u) fp[(1 + t0    ) * TM] = q0;
                if ((unsigned)(t0 + 1) < 8u) fp[(2 + t0    ) * TM] = q1;
                if ((unsigned)(t0 + 2) < 8u) fp[(3 + t0    ) * TM] = q2;
                if ((unsigned)(t0 + 3) < 8u) fp[(4 + t0    ) * TM] = q3;
            }
        }
        __syncthreads();
        // ================= phase B: register-tiled f32x2 GEMM on the chunk =================
        const float* wp = g_Wall + ch * (DCH * NF * OUT_C) + o4;
        #pragma unroll 3
        for (int dj = 0; dj < DCH * NF; dj++) {
            float4 wv = *reinterpret_cast<const float4*>(wp + dj * OUT_C);
            const ulonglong2* ap =
                reinterpret_cast<const ulonglong2*>(feat + dj * TM + rb);
            ulonglong2 A0 = ap[0];   // rows rb..rb+3 (2 f32x2)  -- broadcast LDS
            ulonglong2 A1 = ap[1];   // rows rb+4..rb+7
            unsigned long long a[4] = { A0.x, A0.y, A1.x, A1.y };
            unsigned long long wq[4] = { pack2(wv.x, wv.x), pack2(wv.y, wv.y),
                                         pack2(wv.z, wv.z), pack2(wv.w, wv.w) };
            #pragma unroll
            for (int oi = 0; oi < 4; oi++)
                #pragma unroll
                for (int p = 0; p < 4; p++)
                    acc[oi][p] = ffma2(a[p], wq[oi], acc[oi][p]);
        }
    }

    // ================= epilogue: C[n, o] -> out[n*128 + o] (flat reinterpret) =================
    float* op = out + (row_base + rb) * OUT_C + o4;
    #pragma unroll
    for (int p = 0; p < 4; p++) {
        float2 u0 = unpack2(acc[0][p]);
        float2 u1 = unpack2(acc[1][p]);
        float2 u2 = unpack2(acc[2][p]);
        float2 u3 = unpack2(acc[3][p]);
        float4 lo = make_float4(u0.x, u1.x, u2.x, u3.x);
        float4 hi = make_float4(u0.y, u1.y, u2.y, u3.y);
        *reinterpret_cast<float4*>(op + (2 * p)     * OUT_C) = lo;
        *reinterpret_cast<float4*>(op + (2 * p + 1) * OUT_C) = hi;
    }
}

extern "C" void kernel_launch(void* const* d_in, const int* in_sizes, int n_in,
                              void* d_out, int out_size) {
    const float* x  = (const float*)d_in[0];   // (16, 64, 48, 48)
    const float* wb = (const float*)d_in[1];   // (128, 576)
    const float* ws = (const float*)d_in[2];   // (128, 576, 8)
    const float* sc = (const float*)d_in[3];   // (128, 576)
    float* out = (float*)d_out;                // (16, 128, 48, 48) == flat (36864, 128)

    prep_weights_kernel<<<(IN_DIM * NF * OUT_C + 255) / 256, 256>>>(wb, ws, sc);
    convkan_fused_kernel<<<NROWS / TM, 256>>>(x, out);
}

// round 3
// speedup vs baseline: 4.8198x; 4.8198x over previous
#include <cuda_runtime.h>
#include <cuda_fp16.h>
#include <stdint.h>

#define IN_C    64
#define OUT_C   128
#define HWID    48
#define IMG     2304          // 48*48
#define IN_DIM  576
#define NROWS   36864         // 16 * 2304
#define KTOT    5184          // 576 silu + 576*8 spline features
#define TM      128           // rows per CTA
#define KC      64            // K per chunk
#define NCHUNK  81
#define NSILU   9             // first 9 chunks are silu features
#define NT      256
#define ABUF    16384         // one stage: 128 x 64 fp16

static __device__ __align__(16) __half g_Wt[OUT_C * KTOT];

// ---------------- weight packing: Wt[o][k], k<576 -> base, else spline*scaler ----
__global__ void prep_weights(const float* __restrict__ Wb,
                             const float* __restrict__ Ws,
                             const float* __restrict__ Sc) {
    int idx = blockIdx.x * 256 + threadIdx.x;
    if (idx >= OUT_C * KTOT) return;
    int o = idx / KTOT;
    int k = idx - o * KTOT;
    float v;
    if (k < IN_DIM) {
        v = Wb[o * IN_DIM + k];
    } else {
        int kk = k - IN_DIM;
        int d = kk >> 3, j = kk & 7;
        v = Ws[(o * IN_DIM + d) * 8 + j] * Sc[o * IN_DIM + d];
    }
    g_Wt[idx] = __float2half(v);
}

// ---------------- helpers ----------------
__device__ __forceinline__ uint32_t smem_u32(const void* p) {
    uint32_t a;
    asm("{ .reg .u64 t; cvta.to.shared.u64 t, %1; cvt.u32.u64 %0, t; }" : "=r"(a) : "l"(p));
    return a;
}
__device__ __forceinline__ uint32_t sw_off(uint32_t o) { return o ^ ((o >> 3) & 0x70u); }

__device__ __forceinline__ void ldmx4(uint32_t r[4], uint32_t a) {
    asm volatile("ldmatrix.sync.aligned.m8n8.x4.shared.b16 {%0,%1,%2,%3}, [%4];"
                 : "=r"(r[0]), "=r"(r[1]), "=r"(r[2]), "=r"(r[3]) : "r"(a));
}
__device__ __forceinline__ void mma16816(float c[4], const uint32_t a[4],
                                         uint32_t b0, uint32_t b1) {
    asm volatile("mma.sync.aligned.m16n8k16.row.col.f32.f16.f16.f32 "
                 "{%0,%1,%2,%3}, {%4,%5,%6,%7}, {%8,%9}, {%0,%1,%2,%3};"
                 : "+f"(c[0]), "+f"(c[1]), "+f"(c[2]), "+f"(c[3])
                 : "r"(a[0]), "r"(a[1]), "r"(a[2]), "r"(a[3]), "r"(b0), "r"(b1));
}

__device__ __forceinline__ float fetch_x(const float* __restrict__ xg, int cb, int l,
                                         int khm1, int kwm1) {
    int h = l / HWID;
    int w = l - h * HWID;
    int hh = h + khm1, ww = w + kwm1;
    float v = 0.f;
    if (((unsigned)hh < (unsigned)HWID) && ((unsigned)ww < (unsigned)HWID))
        v = __ldg(xg + cb + hh * HWID + ww);
    return v;
}

__device__ __forceinline__ void fill_b(uint32_t Bb, int chunk, int tid) {
    const __half* wsrc = g_Wt + chunk * KC;
    #pragma unroll
    for (int it = 0; it < 4; ++it) {
        int s = tid + NT * it;
        int o = s >> 3, seg = s & 7;
        uint32_t dst = Bb + sw_off((uint32_t)(o * 128 + seg * 16));
        const void* src = (const void*)(wsrc + (size_t)o * KTOT + seg * 8);
        asm volatile("cp.async.cg.shared.global [%0], [%1], 16;" :: "r"(dst), "l"(src));
    }
}

__device__ __forceinline__ void gen_a(char* Ab, int chunk, const float* __restrict__ xg,
                                      const int* s_cb, const int* s_lb,
                                      const int* s_khw, int tid) {
    if (chunk < NSILU) {
        const int d0 = chunk * KC;
        #pragma unroll 4
        for (int it = 0; it < 16; ++it) {
            int e = tid + NT * it;
            int dp = e & 31, m = e >> 5;
            int cb = s_cb[m], lb = s_lb[m], khw = s_khw[m];
            int kh = (khw >> 8) - 1, kw = (khw & 255) - 1;
            float v0 = fetch_x(xg, cb, lb + d0 + 2 * dp,     kh, kw);
            float v1 = fetch_x(xg, cb, lb + d0 + 2 * dp + 1, kh, kw);
            float s0 = __fdividef(v0, 1.f + __expf(-v0));
            float s1 = __fdividef(v1, 1.f + __expf(-v1));
            __half2 h = __floats2half2_rn(s0, s1);
            *(uint32_t*)(Ab + sw_off((uint32_t)(m * 128 + dp * 4))) =
                *(uint32_t*)&h;
        }
    } else {
        const int d0 = (chunk - NSILU) * 8;
        #pragma unroll
        for (int it = 0; it < 4; ++it) {
            int e = tid + NT * it;
            int dl = e & 7, m = e >> 3;
            int cb = s_cb[m], lb = s_lb[m], khw = s_khw[m];
            int kh = (khw >> 8) - 1, kw = (khw & 255) - 1;
            float v = fetch_x(xg, cb, lb + d0 + dl, kh, kw);
            // cardinal cubic B-spline on uniform extended grid (h=0.4, lo=-1)
            float sv = fmaf(v, 2.5f, 5.5f);
            float fm = floorf(sv);
            int   mm = (int)fm;
            float f  = sv - fm, f2 = f * f, f3 = f2 * f;
            float omf = 1.f - f;
            float q0 = (1.f / 6.f) * omf * omf * omf;
            float q1 = 0.5f * f3 - f2 + (2.f / 3.f);
            float q2 = (1.f / 6.f) + 0.5f * (f + f2 - f3);
            float q3 = (1.f / 6.f) * f3;
            int t0 = mm - 3;
            float bj[8];
            #pragma unroll
            for (int j = 0; j < 8; ++j) {
                int i = j - t0;
                float r = (i == 0) ? q0 : 0.f;
                r = (i == 1) ? q1 : r;
                r = (i == 2) ? q2 : r;
                r = (i == 3) ? q3 : r;
                bj[j] = r;
            }
            __half2 h0 = __floats2half2_rn(bj[0], bj[1]);
            __half2 h1 = __floats2half2_rn(bj[2], bj[3]);
            __half2 h2 = __floats2half2_rn(bj[4], bj[5]);
            __half2 h3 = __floats2half2_rn(bj[6], bj[7]);
            uint4 seg;
            seg.x = *(uint32_t*)&h0;
            seg.y = *(uint32_t*)&h1;
            seg.z = *(uint32_t*)&h2;
            seg.w = *(uint32_t*)&h3;
            *(uint4*)(Ab + sw_off((uint32_t)(m * 128 + dl * 16))) = seg;
        }
    }
}

// ---------------- main fused HMMA kernel ----------------
__global__ void __launch_bounds__(NT, 2)
convkan_mma(const float* __restrict__ xg, float* __restrict__ outg) {
    extern __shared__ char dsm[];                 // [A0|A1|B0|B1] 4*16KB
    __shared__ int s_cb[TM], s_lb[TM], s_khw[TM];

    const uint32_t sbase = smem_u32(dsm);
    const uint32_t sB = sbase + 2 * ABUF;
    const int tid  = threadIdx.x;
    const int wid  = tid >> 5;
    const int lane = tid & 31;
    const int row_base = blockIdx.x * TM;

    if (tid < TM) {
        int n  = row_base + tid;
        int b  = n / IMG;
        int nl = n - b * IMG;
        int i0 = nl >> 2;
        int c  = i0 / 9;
        int t9 = i0 - c * 9;
        int kh = t9 / 3;
        s_cb[tid]  = (b * IN_C + c) * IMG;
        s_lb[tid]  = (nl & 3) * IN_DIM;
        s_khw[tid] = (kh << 8) | (t9 - kh * 3);
    }
    __syncthreads();

    // prologue: stage chunk 0
    fill_b(sB, 0, tid);
    asm volatile("cp.async.commit_group;" ::: "memory");
    gen_a(dsm, 0, xg, s_cb, s_lb, s_khw, tid);

    float acc[2][8][4];
    #pragma unroll
    for (int mi = 0; mi < 2; ++mi)
        #pragma unroll
        for (int nb = 0; nb < 8; ++nb)
            #pragma unroll
            for (int q = 0; q < 4; ++q) acc[mi][nb][q] = 0.f;

    const int wm = (wid & 3) * 32;       // warp row base (4 warps over 128 rows)
    const int wn = (wid >> 2) * 64;      // warp col base (2 warps over 128 cols)
    const uint32_t a_row  = wm + (lane & 15);
    const uint32_t a_koff = (lane >> 4) * 16;
    const uint32_t b_row  = wn + ((lane >> 4) << 3) + (lane & 7);
    const uint32_t b_koff = ((lane >> 3) & 1) * 16;

    for (int c = 0; c < NCHUNK; ++c) {
        const int buf = c & 1;
        if (c + 1 < NCHUNK) {
            fill_b(sB + (buf ^ 1) * ABUF, c + 1, tid);
            asm volatile("cp.async.commit_group;" ::: "memory");
            gen_a(dsm + (buf ^ 1) * ABUF, c + 1, xg, s_cb, s_lb, s_khw, tid);
            asm volatile("cp.async.wait_group 1;" ::: "memory");
        } else {
            asm volatile("cp.async.wait_group 0;" ::: "memory");
        }
        __syncthreads();

        const uint32_t aB = sbase + buf * ABUF;
        const uint32_t bB = sB + buf * ABUF;
        #pragma unroll
        for (int ks = 0; ks < 4; ++ks) {
            const uint32_t kb = ks * 32;
            uint32_t af[2][4];
            ldmx4(af[0], aB + sw_off(a_row * 128u + kb + a_koff));
            ldmx4(af[1], aB + sw_off((a_row + 16) * 128u + kb + a_koff));
            uint32_t bf[4][4];
            #pragma unroll
            for (int g = 0; g < 4; ++g)
                ldmx4(bf[g], bB + sw_off((b_row + g * 16) * 128u + kb + b_koff));
            #pragma unroll
            for (int mi = 0; mi < 2; ++mi)
                #pragma unroll
                for (int nb = 0; nb < 8; ++nb)
                    mma16816(acc[mi][nb], af[mi],
                             bf[nb >> 1][(nb & 1) * 2], bf[nb >> 1][(nb & 1) * 2 + 1]);
        }
        __syncthreads();
    }

    // epilogue: C[n, o] -> out[n*128 + o] (flat reinterpret of (16,128,48,48))
    #pragma unroll
    for (int mi = 0; mi < 2; ++mi) {
        int r0 = row_base + wm + mi * 16 + (lane >> 2);
        float* p0 = outg + (size_t)r0 * OUT_C + wn + (lane & 3) * 2;
        float* p1 = p0 + 8 * OUT_C;
        #pragma unroll
        for (int nb = 0; nb < 8; ++nb) {
            *(float2*)(p0 + nb * 8) = make_float2(acc[mi][nb][0], acc[mi][nb][1]);
            *(float2*)(p1 + nb * 8) = make_float2(acc[mi][nb][2], acc[mi][nb][3]);
        }
    }
}

extern "C" void kernel_launch(void* const* d_in, const int* in_sizes, int n_in,
                              void* d_out, int out_size) {
    const float* x  = (const float*)d_in[0];   // (16, 64, 48, 48)
    const float* wb = (const float*)d_in[1];   // (128, 576)
    const float* ws = (const float*)d_in[2];   // (128, 576, 8)
    const float* sc = (const float*)d_in[3];   // (128, 576)
    float* out = (float*)d_out;                // flat (36864, 128)

    cudaFuncSetAttribute(convkan_mma, cudaFuncAttributeMaxDynamicSharedMemorySize, 4 * ABUF);
    prep_weights<<<(OUT_C * KTOT + 255) / 256, 256>>>(wb, ws, sc);
    convkan_mma<<<NROWS / TM, NT, 4 * ABUF>>>(x, out);
}

// round 4
// speedup vs baseline: 5.8120x; 1.2059x over previous
#include <cuda_runtime.h>
#include <cuda_fp16.h>
#include <stdint.h>

#define IN_C    64
#define OUT_C   128
#define HWID    48
#define IMG     2304          // 48*48
#define IN_DIM  576
#define NROWS   36864         // 16 * 2304
#define KTOT    5184          // 576 silu + 576*8 spline features
#define TM      128           // rows per CTA
#define KC      64            // K per chunk
#define NCHUNK  81
#define NSILU   9             // first 9 chunks are silu features
#define NT      256
#define ABUF    16384         // one stage: 128 x 64 fp16

static __device__ __align__(16) __half g_Wt[OUT_C * KTOT];

// ---------------- weight packing: Wt[o][k], k<576 -> base, else spline*scaler ----
__global__ void prep_weights(const float* __restrict__ Wb,
                             const float* __restrict__ Ws,
                             const float* __restrict__ Sc) {
    int idx = blockIdx.x * 256 + threadIdx.x;
    if (idx >= OUT_C * KTOT) return;
    int o = idx / KTOT;
    int k = idx - o * KTOT;
    float v;
    if (k < IN_DIM) {
        v = Wb[o * IN_DIM + k];
    } else {
        int kk = k - IN_DIM;
        int d = kk >> 3, j = kk & 7;
        v = Ws[(o * IN_DIM + d) * 8 + j] * Sc[o * IN_DIM + d];
    }
    g_Wt[idx] = __float2half(v);
}

// ---------------- helpers ----------------
__device__ __forceinline__ uint32_t smem_u32(const void* p) {
    uint32_t a;
    asm("{ .reg .u64 t; cvta.to.shared.u64 t, %1; cvt.u32.u64 %0, t; }" : "=r"(a) : "l"(p));
    return a;
}
__device__ __forceinline__ uint32_t sw_off(uint32_t o) { return o ^ ((o >> 3) & 0x70u); }

__device__ __forceinline__ void ldmx4(uint32_t r[4], uint32_t a) {
    asm volatile("ldmatrix.sync.aligned.m8n8.x4.shared.b16 {%0,%1,%2,%3}, [%4];"
                 : "=r"(r[0]), "=r"(r[1]), "=r"(r[2]), "=r"(r[3]) : "r"(a));
}
__device__ __forceinline__ void mma16816(float c[4], const uint32_t a[4],
                                         uint32_t b0, uint32_t b1) {
    asm volatile("mma.sync.aligned.m16n8k16.row.col.f32.f16.f16.f32 "
                 "{%0,%1,%2,%3}, {%4,%5,%6,%7}, {%8,%9}, {%0,%1,%2,%3};"
                 : "+f"(c[0]), "+f"(c[1]), "+f"(c[2]), "+f"(c[3])
                 : "r"(a[0]), "r"(a[1]), "r"(a[2]), "r"(a[3]), "r"(b0), "r"(b1));
}

__device__ __forceinline__ void fill_b(uint32_t Bb, int chunk, int tid) {
    const __half* wsrc = g_Wt + chunk * KC;
    #pragma unroll
    for (int it = 0; it < 4; ++it) {
        int s = tid + NT * it;
        int o = s >> 3, seg = s & 7;
        uint32_t dst = Bb + sw_off((uint32_t)(o * 128 + seg * 16));
        const void* src = (const void*)(wsrc + (size_t)o * KTOT + seg * 8);
        asm volatile("cp.async.cg.shared.global [%0], [%1], 16;" :: "r"(dst), "l"(src));
    }
}

// ---------------- main fused HMMA kernel ----------------
__global__ void __launch_bounds__(NT, 2)
convkan_mma(const float* __restrict__ xg, float* __restrict__ outg) {
    extern __shared__ char dsm[];                 // [A0|A1|B0|B1] 4*16KB
    __shared__ int s_cb[TM], s_lb[TM], s_khw[TM];

    const uint32_t sbase = smem_u32(dsm);
    const uint32_t sB = sbase + 2 * ABUF;
    const int tid  = threadIdx.x;
    const int wid  = tid >> 5;
    const int lane = tid & 31;
    const int row_base = blockIdx.x * TM;

    if (tid < TM) {
        int n  = row_base + tid;
        int b  = n / IMG;
        int nl = n - b * IMG;
        int i0 = nl >> 2;
        int c  = i0 / 9;
        int t9 = i0 - c * 9;
        int kh = t9 / 3;
        s_cb[tid]  = (b * IN_C + c) * IMG;
        s_lb[tid]  = (nl & 3) * IN_DIM;
        s_khw[tid] = (kh << 8) | (t9 - kh * 3);
    }
    __syncthreads();

    // ---- persistent incremental coords for spline chunks (4 elems/thread) ----
    int sp_hh[4], sp_w[4];
    #pragma unroll
    for (int it = 0; it < 4; ++it) {
        int e  = tid + NT * it;
        int dl = e & 7, m = e >> 3;
        int l0 = s_lb[m] + dl;
        int h  = l0 / HWID;
        sp_w[it]  = l0 - h * HWID;
        sp_hh[it] = h + ((s_khw[m] >> 8) - 1);
    }

    // ---- silu generator: 2 runs of 16 contiguous k per thread, ONE division each ----
    auto gen_silu = [&](uint32_t Abase, int chunk) {
        const int d0 = chunk * KC;
        #pragma unroll
        for (int it = 0; it < 2; ++it) {
            int e = tid + NT * it;            // 0..511
            int g = e & 3, m = e >> 2;
            int cb   = s_cb[m];
            int khw  = s_khw[m];
            int khm1 = (khw >> 8) - 1, kwm1 = (khw & 255) - 1;
            int l0 = s_lb[m] + d0 + g * 16;
            int h0 = l0 / HWID;
            int w0 = l0 - h0 * HWID;
            uint32_t hv[8];
            #pragma unroll
            for (int j = 0; j < 16; j += 2) {
                float vv[2];
                #pragma unroll
                for (int q = 0; q < 2; ++q) {
                    int w = w0 + j + q, h = h0;
                    if (w >= HWID) { w -= HWID; h += 1; }
                    int hh = h + khm1, ww = w + kwm1;
                    float v = 0.f;
                    if (((unsigned)hh < (unsigned)HWID) && ((unsigned)ww < (unsigned)HWID))
                        v = __ldg(xg + cb + hh * HWID + ww);
                    vv[q] = __fdividef(v, 1.f + __expf(-v));
                }
                __half2 h2 = __floats2half2_rn(vv[0], vv[1]);
                hv[j >> 1] = *reinterpret_cast<uint32_t*>(&h2);
            }
            uint32_t a0 = Abase + sw_off((uint32_t)(m * 128 + g * 32));
            uint32_t a1 = Abase + sw_off((uint32_t)(m * 128 + g * 32 + 16));
            asm volatile("st.shared.v4.b32 [%0], {%1,%2,%3,%4};"
                         :: "r"(a0), "r"(hv[0]), "r"(hv[1]), "r"(hv[2]), "r"(hv[3]) : "memory");
            asm volatile("st.shared.v4.b32 [%0], {%1,%2,%3,%4};"
                         :: "r"(a1), "r"(hv[4]), "r"(hv[5]), "r"(hv[6]), "r"(hv[7]) : "memory");
        }
    };

    // ---- spline generator: incremental coords + zero-fill/scatter stores ----
    auto gen_spline = [&](uint32_t Abase) {
        #pragma unroll
        for (int it = 0; it < 4; ++it) {
            int e  = tid + NT * it;
            int dl = e & 7, m = e >> 3;
            int kwm1 = (s_khw[m] & 255) - 1;
            int hh = sp_hh[it], w = sp_w[it];
            int ww = w + kwm1;
            float v = 0.f;
            if (((unsigned)hh < (unsigned)HWID) && ((unsigned)ww < (unsigned)HWID))
                v = __ldg(xg + s_cb[m] + hh * HWID + ww);
            w += 8;
            if (w >= HWID) { w -= HWID; hh += 1; }
            sp_w[it] = w; sp_hh[it] = hh;

            // cardinal cubic B-spline, uniform extended grid (h=0.4, lo=-1)
            float sv = fmaf(v, 2.5f, 5.5f);
            float fm = floorf(sv);
            float f  = sv - fm, f2 = f * f, f3 = f2 * f;
            float omf = 1.f - f;
            unsigned short q[4];
            q[0] = __half_as_ushort(__float2half_rn((1.f / 6.f) * omf * omf * omf));
            q[1] = __half_as_ushort(__float2half_rn(0.5f * f3 - f2 + (2.f / 3.f)));
            q[2] = __half_as_ushort(__float2half_rn((1.f / 6.f) + 0.5f * (f + f2 - f3)));
            q[3] = __half_as_ushort(__float2half_rn((1.f / 6.f) * f3));
            int t0 = (int)fm - 3;

            uint32_t addr = Abase + sw_off((uint32_t)(m * 128 + dl * 16));
            asm volatile("st.shared.v4.b32 [%0], {%1,%1,%1,%1};"
                         :: "r"(addr), "r"(0u) : "memory");
            #pragma unroll
            for (int i = 0; i < 4; ++i) {
                int j = t0 + i;
                if ((unsigned)j < 8u)
                    asm volatile("st.shared.b16 [%0], %1;"
                                 :: "r"(addr + (uint32_t)(j * 2)), "h"(q[i]) : "memory");
            }
        }
    };

    // ---- prologue: stage chunk 0 ----
    fill_b(sB, 0, tid);
    asm volatile("cp.async.commit_group;" ::: "memory");
    gen_silu(sbase, 0);

    float acc[2][8][4];
    #pragma unroll
    for (int mi = 0; mi < 2; ++mi)
        #pragma unroll
        for (int nb = 0; nb < 8; ++nb)
            #pragma unroll
            for (int q = 0; q < 4; ++q) acc[mi][nb][q] = 0.f;

    const int wm = (wid & 3) * 32;       // warp row base (4 warps over 128 rows)
    const int wn = (wid >> 2) * 64;      // warp col base (2 warps over 128 cols)
    const uint32_t a_row  = wm + (lane & 15);
    const uint32_t a_koff = (lane >> 4) * 16;
    const uint32_t b_row  = wn + ((lane >> 4) << 3) + (lane & 7);
    const uint32_t b_koff = ((lane >> 3) & 1) * 16;

    for (int c = 0; c < NCHUNK; ++c) {
        const int buf = c & 1;
        if (c + 1 < NCHUNK) {
            fill_b(sB + (buf ^ 1) * ABUF, c + 1, tid);
            asm volatile("cp.async.commit_group;" ::: "memory");
            if (c + 1 < NSILU) gen_silu(sbase + (buf ^ 1) * ABUF, c + 1);
            else               gen_spline(sbase + (buf ^ 1) * ABUF);
            asm volatile("cp.async.wait_group 1;" ::: "memory");
        } else {
            asm volatile("cp.async.wait_group 0;" ::: "memory");
        }
        __syncthreads();

        const uint32_t aB = sbase + buf * ABUF;
        const uint32_t bB = sB + buf * ABUF;
        #pragma unroll
        for (int ks = 0; ks < 4; ++ks) {
            const uint32_t kb = ks * 32;
            uint32_t af[2][4];
            ldmx4(af[0], aB + sw_off(a_row * 128u + kb + a_koff));
            ldmx4(af[1], aB + sw_off((a_row + 16) * 128u + kb + a_koff));
            uint32_t bf[4][4];
            #pragma unroll
            for (int g = 0; g < 4; ++g)
                ldmx4(bf[g], bB + sw_off((b_row + g * 16) * 128u + kb + b_koff));
            #pragma unroll
            for (int mi = 0; mi < 2; ++mi)
                #pragma unroll
                for (int nb = 0; nb < 8; ++nb)
                    mma16816(acc[mi][nb], af[mi],
                             bf[nb >> 1][(nb & 1) * 2], bf[nb >> 1][(nb & 1) * 2 + 1]);
        }
        __syncthreads();
    }

    // epilogue: C[n, o] -> out[n*128 + o] (flat reinterpret of (16,128,48,48))
    #pragma unroll
    for (int mi = 0; mi < 2; ++mi) {
        int r0 = row_base + wm + mi * 16 + (lane >> 2);
        float* p0 = outg + (size_t)r0 * OUT_C + wn + (lane & 3) * 2;
        float* p1 = p0 + 8 * OUT_C;
        #pragma unroll
        for (int nb = 0; nb < 8; ++nb) {
            *(float2*)(p0 + nb * 8) = make_float2(acc[mi][nb][0], acc[mi][nb][1]);
            *(float2*)(p1 + nb * 8) = make_float2(acc[mi][nb][2], acc[mi][nb][3]);
        }
    }
}

extern "C" void kernel_launch(void* const* d_in, const int* in_sizes, int n_in,
                              void* d_out, int out_size) {
    const float* x  = (const float*)d_in[0];   // (16, 64, 48, 48)
    const float* wb = (const float*)d_in[1];   // (128, 576)
    const float* ws = (const float*)d_in[2];   // (128, 576, 8)
    const float* sc = (const float*)d_in[3];   // (128, 576)
    float* out = (float*)d_out;                // flat (36864, 128)

    cudaFuncSetAttribute(convkan_mma, cudaFuncAttributeMaxDynamicSharedMemorySize, 4 * ABUF);
    prep_weights<<<(OUT_C * KTOT + 255) / 256, 256>>>(wb, ws, sc);
    convkan_mma<<<NROWS / TM, NT, 4 * ABUF>>>(x, out);
}